// round 9
// baseline (speedup 1.0000x reference)
#include <cuda_runtime.h>
#include <cuda_bf16.h>
#include <math.h>
#include <stdint.h>

// ---------------------------------------------------------------------------
// TransformerBlock (3x3 neighborhood attention). bf16 mma.sync GEMMs
// (fp32 accum), 64x64 warp tiles (4 warps/CTA), fused QKV, bf16 attention
// operands, fc2 epilogue writes transposed [B,C,H,W] output directly.
// ---------------------------------------------------------------------------

#define N_TOK 65536
#define CCH   256
#define HIDN  1024
#define HW    16384
#define WD    128
#define EPSF  1e-5f

__device__ float          g_xc [(size_t)N_TOK * CCH];
__device__ __nv_bfloat16  g_n1 [(size_t)N_TOK * CCH];
__device__ __nv_bfloat16  g_qkv[(size_t)N_TOK * 768];
__device__ float          g_x1 [(size_t)N_TOK * CCH];
__device__ __nv_bfloat16  g_n2 [(size_t)N_TOK * CCH];
__device__ __nv_bfloat16  g_h  [(size_t)N_TOK * HIDN];

__device__ __nv_bfloat16 g_wqkv_t[768 * CCH];   // q 0-255, k 256-511, v 512-767
__device__ __nv_bfloat16 g_w1_t[(size_t)HIDN * CCH];
__device__ __nv_bfloat16 g_w2_t[(size_t)CCH * HIDN];
__device__ float         g_bqkv[768];

// ---------------------------------------------------------------------------
// Combined prep: transpose+bf16-round all 5 weights, copy fused QKV bias.
// Block = (32,8). Block ranges: [0,64) wq, [64,128) wk, [128,192) wv,
// [192,448) fc1 (N=1024: 32x8 tiles), [448,704) fc2 (K=1024: 8x32 tiles).
// ---------------------------------------------------------------------------
__global__ void wprep_kernel(const float* __restrict__ wq, const float* __restrict__ wk,
                             const float* __restrict__ wv, const float* __restrict__ w1,
                             const float* __restrict__ w2, const float* __restrict__ bq,
                             const float* __restrict__ bk, const float* __restrict__ bv)
{
    __shared__ float t[32][33];
    int tx = threadIdx.x, ty = threadIdx.y;
    int tid = ty * 32 + tx;
    int bid = blockIdx.x;

    const float* src; __nv_bfloat16* dst; int K, N, lb;
    if (bid < 192) {
        K = 256; N = 256;
        int m = bid >> 6;             // 0,1,2
        lb = bid & 63;
        src = (m == 0) ? wq : (m == 1) ? wk : wv;
        dst = g_wqkv_t + m * 256 * 256;
        if (lb == 0) {
            const float* bs = (m == 0) ? bq : (m == 1) ? bk : bv;
            g_bqkv[m * 256 + tid] = bs[tid];
        }
    } else if (bid < 448) {
        K = 256; N = 1024; lb = bid - 192;
        src = w1; dst = g_w1_t;
    } else {
        K = 1024; N = 256; lb = bid - 448;
        src = w2; dst = g_w2_t;
    }
    int nx = N >> 5;
    int n0 = (lb % nx) << 5;
    int k0 = (lb / nx) << 5;

#pragma unroll
    for (int j = 0; j < 4; j++)
        t[ty + j * 8][tx] = src[(size_t)(k0 + ty + j * 8) * N + n0 + tx];
    __syncthreads();
#pragma unroll
    for (int j = 0; j < 4; j++)
        dst[(size_t)(n0 + ty + j * 8) * K + k0 + tx] = __float2bfloat16(t[tx][ty + j * 8]);
}

// ---------------------------------------------------------------------------
// LN1 + transpose [B,C,H,W] -> [N,C]; n1 stored bf16
// ---------------------------------------------------------------------------
__global__ __launch_bounds__(256) void ln1_kernel(const float* __restrict__ x,
                                                  const float* __restrict__ gam,
                                                  const float* __restrict__ bet)
{
    __shared__ float s[256][33];
    __shared__ float mu[32], rs[32];
    int tid = threadIdx.x;
    int tx = tid & 31, ty = tid >> 5;
    int blk = blockIdx.x;
    int b  = blk >> 9;
    int p0 = (blk & 511) << 5;

    const float* xb = x + ((size_t)b * CCH) * HW + p0 + tx;
#pragma unroll
    for (int i = 0; i < 32; i++) {
        int c = ty * 32 + i;
        s[c][tx] = xb[(size_t)c * HW];
    }
    __syncthreads();
    {
        int px = ty * 4 + (tx >> 3);
        int j  = tx & 7;
        float s1 = 0.f, s2 = 0.f;
#pragma unroll
        for (int m = 0; m < 32; m++) {
            float vv = s[j + 8 * m][px];
            s1 += vv; s2 += vv * vv;
        }
#pragma unroll
        for (int off = 4; off >= 1; off >>= 1) {
            s1 += __shfl_xor_sync(0xffffffffu, s1, off);
            s2 += __shfl_xor_sync(0xffffffffu, s2, off);
        }
        if (j == 0) {
            float m1  = s1 * (1.f / 256.f);
            float var = fmaxf(s2 * (1.f / 256.f) - m1 * m1, 0.f);
            mu[px] = m1;
            rs[px] = rsqrtf(var + EPSF);
        }
    }
    __syncthreads();

    float gr = gam[tid], br = bet[tid];
    size_t tbase = ((size_t)b * HW + p0) * CCH + tid;
#pragma unroll
    for (int j = 0; j < 32; j++) {
        float xv = s[tid][j];
        g_xc[tbase + (size_t)j * CCH] = xv;
        g_n1[tbase + (size_t)j * CCH] =
            __float2bfloat16((xv - mu[j]) * rs[j] * gr + br);
    }
}

// ---------------------------------------------------------------------------
// bf16 GEMM: C[M,N] = A[M,K] @ Bt[N,K]^T + bias (+epi), fp32 accum.
// 128x128 tile, BK=32, 4 warps (warp tile 64x64), 3-stage cp.async.
// Smem rows: 32 bf16 = 64B, chunk swizzle c ^= (row>>1)&3.
// epi: 0 bias (bf16 out); 1 bias+GELU (bf16 out);
//      2 bias+residual -> transposed fp32 [B,C,H,W] write (N must be 256).
// ---------------------------------------------------------------------------
#define TILE_BYTES 8192                    // 128 rows * 64 B
#define STAGE_BYTES (2 * TILE_BYTES)
#define NSTAGE 3
#define SMEM_TOTAL (NSTAGE * STAGE_BYTES)  // 49152

__device__ __forceinline__ void cpasync16(uint32_t dst, const void* src) {
    asm volatile("cp.async.cg.shared.global [%0], [%1], 16;" :: "r"(dst), "l"(src));
}
__device__ __forceinline__ void ldsm4(uint32_t& r0, uint32_t& r1, uint32_t& r2,
                                      uint32_t& r3, uint32_t addr) {
    asm volatile("ldmatrix.sync.aligned.m8n8.x4.shared.b16 {%0,%1,%2,%3}, [%4];"
                 : "=r"(r0), "=r"(r1), "=r"(r2), "=r"(r3) : "r"(addr));
}
__device__ __forceinline__ void mma_bf16(float* c, const uint32_t* a, const uint32_t* b) {
    asm volatile(
        "mma.sync.aligned.m16n8k16.row.col.f32.bf16.bf16.f32 "
        "{%0,%1,%2,%3},{%4,%5,%6,%7},{%8,%9},{%0,%1,%2,%3};"
        : "+f"(c[0]), "+f"(c[1]), "+f"(c[2]), "+f"(c[3])
        : "r"(a[0]), "r"(a[1]), "r"(a[2]), "r"(a[3]), "r"(b[0]), "r"(b[1]));
}

__global__ __launch_bounds__(128) void bgemm_kernel(
    const __nv_bfloat16* __restrict__ A, const __nv_bfloat16* __restrict__ Bt,
    const float* __restrict__ bias, const float* __restrict__ res,
    void* __restrict__ Cv, int N, int K, int epi)
{
    extern __shared__ uint8_t smem[];
    int tid = threadIdx.x;
    int bx = blockIdx.x, by = blockIdx.y;
    int lane = tid & 31, warp = tid >> 5;
    int wm = warp >> 1, wn = warp & 1;

    const __nv_bfloat16* Ag  = A  + (size_t)by * 128 * K;
    const __nv_bfloat16* Btg = Bt + (size_t)bx * 128 * K;

    // cp.async: each thread loads one full 64B row (4 chunks) of A and of B
    int r = tid;
    int wkey = (r >> 1) & 3;
    uint32_t sBase = (uint32_t)__cvta_generic_to_shared(smem);
    const __nv_bfloat16* Asrc = Ag  + (size_t)r * K;
    const __nv_bfloat16* Bsrc = Btg + (size_t)r * K;
    uint32_t rowA = sBase + r * 64;

    // fragment addressing
    int fkey  = ((lane & 15) >> 1) & 3;
    int khalf = lane >> 4;
    uint32_t aRow = (uint32_t)(wm * 64 + (lane & 15)) * 64;
    uint32_t bRow = (uint32_t)TILE_BYTES + (uint32_t)(wn * 64 + (lane & 15)) * 64;

    float acc[4][8][4];
#pragma unroll
    for (int i = 0; i < 4; i++)
#pragma unroll
        for (int j = 0; j < 8; j++)
#pragma unroll
            for (int k = 0; k < 4; k++) acc[i][j][k] = 0.f;

    int niter = K >> 5;

#pragma unroll
    for (int p = 0; p < 2; p++) {
        uint32_t sb = p * STAGE_BYTES;
        int k0 = p << 5;
#pragma unroll
        for (int c = 0; c < 4; c++) {
            uint32_t so = (uint32_t)((c ^ wkey) << 4);
            cpasync16(rowA + sb + so, Asrc + k0 + c * 8);
            cpasync16(rowA + sb + TILE_BYTES + so, Bsrc + k0 + c * 8);
        }
        asm volatile("cp.async.commit_group;");
    }

    int st = 0;
    for (int it = 0; it < niter; ++it) {
        int pre = it + 2;
        if (pre < niter) {
            int ps = pre % NSTAGE;
            uint32_t sb = ps * STAGE_BYTES;
            int k0 = pre << 5;
#pragma unroll
            for (int c = 0; c < 4; c++) {
                uint32_t so = (uint32_t)((c ^ wkey) << 4);
                cpasync16(rowA + sb + so, Asrc + k0 + c * 8);
                cpasync16(rowA + sb + TILE_BYTES + so, Bsrc + k0 + c * 8);
            }
        }
        asm volatile("cp.async.commit_group;");
        asm volatile("cp.async.wait_group 2;" ::: "memory");
        __syncthreads();

        uint32_t stb = st * STAGE_BYTES;
#pragma unroll
        for (int s = 0; s < 2; s++) {
            int chunk = s * 2 + khalf;
            uint32_t aoff = sBase + stb + aRow + ((chunk ^ fkey) * 16);
            uint32_t boff = sBase + stb + bRow + ((chunk ^ fkey) * 16);
            uint32_t a[4][4], b[8][2];
#pragma unroll
            for (int mi = 0; mi < 4; mi++)
                ldsm4(a[mi][0], a[mi][1], a[mi][2], a[mi][3], aoff + mi * 1024);
#pragma unroll
            for (int h = 0; h < 4; h++) {
                uint32_t q0, q1, q2, q3;
                ldsm4(q0, q1, q2, q3, boff + h * 1024);
                b[h * 2][0]     = q0; b[h * 2][1]     = q2;
                b[h * 2 + 1][0] = q1; b[h * 2 + 1][1] = q3;
            }
#pragma unroll
            for (int mi = 0; mi < 4; mi++)
#pragma unroll
                for (int ni = 0; ni < 8; ni++)
                    mma_bf16(acc[mi][ni], a[mi], b[ni]);
        }
        __syncthreads();
        st = (st + 1) % NSTAGE;
    }

    if (epi == 2) {
        // bias + residual, then transpose through smem and write [B,C,H,W].
        float* smf = (float*)smem;              // [64][132] fp32 = 33792 B
        float* outp = (float*)Cv;
        int t0 = by * 128;
        int b  = t0 >> 14;
        int p0 = t0 & (HW - 1);
        int c0 = bx * 128;
#pragma unroll
        for (int h = 0; h < 2; h++) {
            __syncthreads();
            if (wn == h) {
#pragma unroll
                for (int ni = 0; ni < 8; ni++) {
                    int cl = wn * 64 + ni * 8 + (lane & 3) * 2;   // 0..127
                    int cg = c0 + cl;
                    float bi0 = bias[cg], bi1 = bias[cg + 1];
                    int cc = cl & 63;
#pragma unroll
                    for (int mi = 0; mi < 4; mi++) {
                        int rl = wm * 64 + mi * 16 + (lane >> 2);
                        size_t rg = (size_t)(t0 + rl);
                        float2 r0 = *(const float2*)(res + rg * 256 + cg);
                        float2 r1 = *(const float2*)(res + (rg + 8) * 256 + cg);
                        smf[cc * 132 + rl]           = acc[mi][ni][0] + bi0 + r0.x;
                        smf[(cc + 1) * 132 + rl]     = acc[mi][ni][1] + bi1 + r0.y;
                        smf[cc * 132 + rl + 8]       = acc[mi][ni][2] + bi0 + r1.x;
                        smf[(cc + 1) * 132 + rl + 8] = acc[mi][ni][3] + bi1 + r1.y;
                    }
                }
            }
            __syncthreads();
            int ch = tid >> 1, seg = tid & 1;
            float* op = outp + ((size_t)b * CCH + c0 + h * 64 + ch) * HW + p0 + seg * 64;
            const float* sp = smf + ch * 132 + seg * 64;
#pragma unroll
            for (int j = 0; j < 16; j++)
                ((float4*)op)[j] = ((const float4*)sp)[j];
        }
        return;
    }

    // epi 0/1: bf16 output
    int colBase = bx * 128 + wn * 64;
    int rowBase = by * 128 + wm * 64 + (lane >> 2);
    __nv_bfloat16* Cb = (__nv_bfloat16*)Cv;
#pragma unroll
    for (int ni = 0; ni < 8; ni++) {
        int c = colBase + ni * 8 + (lane & 3) * 2;
        float bi0 = bias[c], bi1 = bias[c + 1];
#pragma unroll
        for (int mi = 0; mi < 4; mi++) {
            int rr = rowBase + mi * 16;
            float v00 = acc[mi][ni][0] + bi0;
            float v01 = acc[mi][ni][1] + bi1;
            float v10 = acc[mi][ni][2] + bi0;
            float v11 = acc[mi][ni][3] + bi1;
            if (epi == 1) {
                v00 = 0.5f * v00 * (1.f + erff(v00 * 0.70710678118654752f));
                v01 = 0.5f * v01 * (1.f + erff(v01 * 0.70710678118654752f));
                v10 = 0.5f * v10 * (1.f + erff(v10 * 0.70710678118654752f));
                v11 = 0.5f * v11 * (1.f + erff(v11 * 0.70710678118654752f));
            }
            *(__nv_bfloat162*)(Cb + (size_t)rr * N + c) =
                __floats2bfloat162_rn(v00, v01);
            *(__nv_bfloat162*)(Cb + (size_t)(rr + 8) * N + c) =
                __floats2bfloat162_rn(v10, v11);
        }
    }
}

// ---------------------------------------------------------------------------
// 3x3 neighborhood attention + residual + fused LN2; q/k/v bf16 packed [N,768]
// ---------------------------------------------------------------------------
__global__ __launch_bounds__(256) void attn_kernel(const float* __restrict__ g2,
                                                   const float* __restrict__ b2)
{
    int lane = threadIdx.x & 31;
    int warp = threadIdx.x >> 5;
    int t = blockIdx.x * 8 + warp;
    int p = t & (HW - 1);
    int yy = p >> 7, xx = p & 127;

    const __nv_bfloat162* qp = (const __nv_bfloat162*)(g_qkv + (size_t)t * 768) + lane;
    float2 ql[4];
#pragma unroll
    for (int i = 0; i < 4; i++) ql[i] = __bfloat1622float2(qp[32 * i]);

    float sc[9];
    int tns[9];
    unsigned vmask = 0;
#pragma unroll
    for (int n = 0; n < 9; n++) {
        int dy = n / 3 - 1, dx = n % 3 - 1;
        int ny = yy + dy, nx = xx + dx;
        bool valid = ((unsigned)ny < 128u) && ((unsigned)nx < 128u);
        int tn = t + dy * WD + dx;
        tns[n] = tn;
        if (valid) {
            vmask |= 1u << n;
            const __nv_bfloat162* kp =
                (const __nv_bfloat162*)(g_qkv + (size_t)tn * 768 + 256) + lane;
            float dot = 0.f;
#pragma unroll
            for (int i = 0; i < 4; i++) {
                float2 kv = __bfloat1622float2(kp[32 * i]);
                dot += ql[i].x * kv.x + ql[i].y * kv.y;
            }
#pragma unroll
            for (int off = 16; off >= 1; off >>= 1)
                dot += __shfl_xor_sync(0xffffffffu, dot, off);
            sc[n] = dot * (1.0f / 16.0f);
        } else {
            sc[n] = -1e30f;
        }
    }

    float mx = sc[0];
#pragma unroll
    for (int n = 1; n < 9; n++) mx = fmaxf(mx, sc[n]);
    float w[9], wsum = 0.f;
#pragma unroll
    for (int n = 0; n < 9; n++) {
        w[n] = ((vmask >> n) & 1u) ? expf(sc[n] - mx) : 0.f;
        wsum += w[n];
    }
    float inv = 1.f / wsum;

    float2 acc[4];
#pragma unroll
    for (int i = 0; i < 4; i++) acc[i] = make_float2(0.f, 0.f);
#pragma unroll
    for (int n = 0; n < 9; n++) {
        if ((vmask >> n) & 1u) {
            float wn = w[n] * inv;
            const __nv_bfloat162* vp =
                (const __nv_bfloat162*)(g_qkv + (size_t)tns[n] * 768 + 512) + lane;
#pragma unroll
            for (int i = 0; i < 4; i++) {
                float2 vv = __bfloat1622float2(vp[32 * i]);
                acc[i].x += wn * vv.x;
                acc[i].y += wn * vv.y;
            }
        }
    }

    const float2* xp = (const float2*)(g_xc + (size_t)t * CCH) + lane;
    float2 xv[4];
    float s1 = 0.f, s2 = 0.f;
#pragma unroll
    for (int i = 0; i < 4; i++) {
        float2 xr = xp[32 * i];
        xv[i].x = xr.x + acc[i].x;
        xv[i].y = xr.y + acc[i].y;
        s1 += xv[i].x + xv[i].y;
        s2 += xv[i].x * xv[i].x + xv[i].y * xv[i].y;
    }
#pragma unroll
    for (int off = 16; off >= 1; off >>= 1) {
        s1 += __shfl_xor_sync(0xffffffffu, s1, off);
        s2 += __shfl_xor_sync(0xffffffffu, s2, off);
    }
    float m1  = s1 * (1.f / 256.f);
    float var = fmaxf(s2 * (1.f / 256.f) - m1 * m1, 0.f);
    float rstd = rsqrtf(var + EPSF);

    float2* x1p = (float2*)(g_x1 + (size_t)t * CCH) + lane;
    __nv_bfloat162* n2p = (__nv_bfloat162*)(g_n2 + (size_t)t * CCH) + lane;
    const float2* g2p = (const float2*)g2 + lane;
    const float2* b2p = (const float2*)b2 + lane;
#pragma unroll
    for (int i = 0; i < 4; i++) {
        float2 gg = g2p[32 * i], bb = b2p[32 * i];
        x1p[32 * i] = xv[i];
        n2p[32 * i] = __floats2bfloat162_rn(
            (xv[i].x - m1) * rstd * gg.x + bb.x,
            (xv[i].y - m1) * rstd * gg.y + bb.y);
    }
}

// ---------------------------------------------------------------------------
extern "C" void kernel_launch(void* const* d_in, const int* in_sizes, int n_in,
                              void* d_out, int out_size)
{
    (void)in_sizes; (void)n_in; (void)out_size;
    const float* x     = (const float*)d_in[0];
    const float* wq    = (const float*)d_in[1];
    const float* bq    = (const float*)d_in[2];
    const float* wk    = (const float*)d_in[3];
    const float* bk    = (const float*)d_in[4];
    const float* wv    = (const float*)d_in[5];
    const float* bv    = (const float*)d_in[6];
    const float* ln1_g = (const float*)d_in[7];
    const float* ln1_b = (const float*)d_in[8];
    const float* ln2_g = (const float*)d_in[9];
    const float* ln2_b = (const float*)d_in[10];
    const float* fc1_w = (const float*)d_in[11];
    const float* fc1_b = (const float*)d_in[12];
    const float* fc2_w = (const float*)d_in[13];
    const float* fc2_b = (const float*)d_in[14];
    float* out = (float*)d_out;

    __nv_bfloat16 *pn1, *pn2, *ph, *pwqkv, *pw1, *pw2, *pqkv;
    float *px1, *pbqkv;
    cudaGetSymbolAddress((void**)&pn1,   g_n1);
    cudaGetSymbolAddress((void**)&pn2,   g_n2);
    cudaGetSymbolAddress((void**)&ph,    g_h);
    cudaGetSymbolAddress((void**)&pwqkv, g_wqkv_t);
    cudaGetSymbolAddress((void**)&pw1,   g_w1_t);
    cudaGetSymbolAddress((void**)&pw2,   g_w2_t);
    cudaGetSymbolAddress((void**)&pqkv,  g_qkv);
    cudaGetSymbolAddress((void**)&px1,   g_x1);
    cudaGetSymbolAddress((void**)&pbqkv, g_bqkv);

    cudaFuncSetAttribute(bgemm_kernel,
                         cudaFuncAttributeMaxDynamicSharedMemorySize, SMEM_TOTAL);

    // all weight transposes + bias packing in one launch
    wprep_kernel<<<704, dim3(32, 8)>>>(wq, wk, wv, fc1_w, fc2_w, bq, bk, bv);

    ln1_kernel<<<2048, 256>>>(x, ln1_g, ln1_b);

    // fused QKV: M=65536, N=768, K=256 -> bf16
    bgemm_kernel<<<dim3(6, 512), 128, SMEM_TOTAL>>>(pn1, pwqkv, pbqkv, nullptr,
                                                    pqkv, 768, 256, 0);

    attn_kernel<<<8192, 256>>>(ln2_g, ln2_b);

    // fc1 + GELU -> bf16 h
    bgemm_kernel<<<dim3(8, 512), 128, SMEM_TOTAL>>>(pn2, pw1, fc1_b, nullptr,
                                                    ph, 1024, 256, 1);
    // fc2 + bias + residual -> transposed fp32 out
    bgemm_kernel<<<dim3(2, 512), 128, SMEM_TOTAL>>>(ph, pw2, fc2_b, px1,
                                                    out, 256, 1024, 2);
}

// round 10
// speedup vs baseline: 1.2924x; 1.2924x over previous
#include <cuda_runtime.h>
#include <cuda_bf16.h>
#include <math.h>
#include <stdint.h>

// ---------------------------------------------------------------------------
// TransformerBlock (3x3 neighborhood attention). bf16 mma.sync GEMMs
// (fp32 accum), 8 warps / 64x32 warp tiles (R7 config), fused QKV,
// bf16 attention operands, fc2 epilogue writes transposed [B,C,H,W] directly.
// ---------------------------------------------------------------------------

#define N_TOK 65536
#define CCH   256
#define HIDN  1024
#define HW    16384
#define WD    128
#define EPSF  1e-5f

__device__ float          g_xc [(size_t)N_TOK * CCH];
__device__ __nv_bfloat16  g_n1 [(size_t)N_TOK * CCH];
__device__ __nv_bfloat16  g_qkv[(size_t)N_TOK * 768];
__device__ float          g_x1 [(size_t)N_TOK * CCH];
__device__ __nv_bfloat16  g_n2 [(size_t)N_TOK * CCH];
__device__ __nv_bfloat16  g_h  [(size_t)N_TOK * HIDN];

__device__ __nv_bfloat16 g_wqkv_t[768 * CCH];   // q 0-255, k 256-511, v 512-767
__device__ __nv_bfloat16 g_w1_t[(size_t)HIDN * CCH];
__device__ __nv_bfloat16 g_w2_t[(size_t)CCH * HIDN];
__device__ float         g_bqkv[768];

// ---------------------------------------------------------------------------
// Combined prep: transpose+bf16-round all 5 weights, copy fused QKV bias.
// Block = (32,8). Block ranges: [0,64) wq, [64,128) wk, [128,192) wv,
// [192,448) fc1, [448,704) fc2.
// ---------------------------------------------------------------------------
__global__ void wprep_kernel(const float* __restrict__ wq, const float* __restrict__ wk,
                             const float* __restrict__ wv, const float* __restrict__ w1,
                             const float* __restrict__ w2, const float* __restrict__ bq,
                             const float* __restrict__ bk, const float* __restrict__ bv)
{
    __shared__ float t[32][33];
    int tx = threadIdx.x, ty = threadIdx.y;
    int tid = ty * 32 + tx;
    int bid = blockIdx.x;

    const float* src; __nv_bfloat16* dst; int K, N, lb;
    if (bid < 192) {
        K = 256; N = 256;
        int m = bid >> 6;
        lb = bid & 63;
        src = (m == 0) ? wq : (m == 1) ? wk : wv;
        dst = g_wqkv_t + m * 256 * 256;
        if (lb == 0) {
            const float* bs = (m == 0) ? bq : (m == 1) ? bk : bv;
            g_bqkv[m * 256 + tid] = bs[tid];
        }
    } else if (bid < 448) {
        K = 256; N = 1024; lb = bid - 192;
        src = w1; dst = g_w1_t;
    } else {
        K = 1024; N = 256; lb = bid - 448;
        src = w2; dst = g_w2_t;
    }
    int nx = N >> 5;
    int n0 = (lb % nx) << 5;
    int k0 = (lb / nx) << 5;

#pragma unroll
    for (int j = 0; j < 4; j++)
        t[ty + j * 8][tx] = src[(size_t)(k0 + ty + j * 8) * N + n0 + tx];
    __syncthreads();
#pragma unroll
    for (int j = 0; j < 4; j++)
        dst[(size_t)(n0 + ty + j * 8) * K + k0 + tx] = __float2bfloat16(t[tx][ty + j * 8]);
}

// ---------------------------------------------------------------------------
// LN1 + transpose [B,C,H,W] -> [N,C]; n1 stored bf16
// ---------------------------------------------------------------------------
__global__ __launch_bounds__(256) void ln1_kernel(const float* __restrict__ x,
                                                  const float* __restrict__ gam,
                                                  const float* __restrict__ bet)
{
    __shared__ float s[256][33];
    __shared__ float mu[32], rs[32];
    int tid = threadIdx.x;
    int tx = tid & 31, ty = tid >> 5;
    int blk = blockIdx.x;
    int b  = blk >> 9;
    int p0 = (blk & 511) << 5;

    const float* xb = x + ((size_t)b * CCH) * HW + p0 + tx;
#pragma unroll
    for (int i = 0; i < 32; i++) {
        int c = ty * 32 + i;
        s[c][tx] = xb[(size_t)c * HW];
    }
    __syncthreads();
    {
        int px = ty * 4 + (tx >> 3);
        int j  = tx & 7;
        float s1 = 0.f, s2 = 0.f;
#pragma unroll
        for (int m = 0; m < 32; m++) {
            float vv = s[j + 8 * m][px];
            s1 += vv; s2 += vv * vv;
        }
#pragma unroll
        for (int off = 4; off >= 1; off >>= 1) {
            s1 += __shfl_xor_sync(0xffffffffu, s1, off);
            s2 += __shfl_xor_sync(0xffffffffu, s2, off);
        }
        if (j == 0) {
            float m1  = s1 * (1.f / 256.f);
            float var = fmaxf(s2 * (1.f / 256.f) - m1 * m1, 0.f);
            mu[px] = m1;
            rs[px] = rsqrtf(var + EPSF);
        }
    }
    __syncthreads();

    float gr = gam[tid], br = bet[tid];
    size_t tbase = ((size_t)b * HW + p0) * CCH + tid;
#pragma unroll
    for (int j = 0; j < 32; j++) {
        float xv = s[tid][j];
        g_xc[tbase + (size_t)j * CCH] = xv;
        g_n1[tbase + (size_t)j * CCH] =
            __float2bfloat16((xv - mu[j]) * rs[j] * gr + br);
    }
}

// ---------------------------------------------------------------------------
// bf16 GEMM: C[M,N] = A[M,K] @ Bt[N,K]^T + bias (+epi), fp32 accum.
// 128x128 tile, BK=32, 8 warps (warp tile 64x32), 3-stage cp.async.
// epi: 0 bias (bf16 out); 1 bias+GELU (bf16 out);
//      2 bias+residual -> transposed fp32 [B,C,H,W] write (N must be 256).
// ---------------------------------------------------------------------------
#define TILE_BYTES 8192
#define STAGE_BYTES (2 * TILE_BYTES)
#define NSTAGE 3
#define SMEM_TOTAL (NSTAGE * STAGE_BYTES)  // 49152

__device__ __forceinline__ void cpasync16(uint32_t dst, const void* src) {
    asm volatile("cp.async.cg.shared.global [%0], [%1], 16;" :: "r"(dst), "l"(src));
}
__device__ __forceinline__ void ldsm4(uint32_t& r0, uint32_t& r1, uint32_t& r2,
                                      uint32_t& r3, uint32_t addr) {
    asm volatile("ldmatrix.sync.aligned.m8n8.x4.shared.b16 {%0,%1,%2,%3}, [%4];"
                 : "=r"(r0), "=r"(r1), "=r"(r2), "=r"(r3) : "r"(addr));
}
__device__ __forceinline__ void mma_bf16(float* c, const uint32_t* a, const uint32_t* b) {
    asm volatile(
        "mma.sync.aligned.m16n8k16.row.col.f32.bf16.bf16.f32 "
        "{%0,%1,%2,%3},{%4,%5,%6,%7},{%8,%9},{%0,%1,%2,%3};"
        : "+f"(c[0]), "+f"(c[1]), "+f"(c[2]), "+f"(c[3])
        : "r"(a[0]), "r"(a[1]), "r"(a[2]), "r"(a[3]), "r"(b[0]), "r"(b[1]));
}

__global__ __launch_bounds__(256) void bgemm_kernel(
    const __nv_bfloat16* __restrict__ A, const __nv_bfloat16* __restrict__ Bt,
    const float* __restrict__ bias, const float* __restrict__ res,
    void* __restrict__ Cv, int N, int K, int epi)
{
    extern __shared__ uint8_t smem[];
    int tid = threadIdx.x;
    int bx = blockIdx.x, by = blockIdx.y;
    int lane = tid & 31, warp = tid >> 5;
    int wm = warp >> 2, wn = warp & 3;

    const __nv_bfloat16* Ag  = A  + (size_t)by * 128 * K;
    const __nv_bfloat16* Btg = Bt + (size_t)bx * 128 * K;

    // cp.async: thread -> row r, chunk pair cp,cp+1 (16B chunks of 8 bf16)
    int r  = tid >> 1;
    int cp = (tid & 1) * 2;
    int wkey = (r >> 1) & 3;
    uint32_t sBase = (uint32_t)__cvta_generic_to_shared(smem);
    const __nv_bfloat16* Asrc = Ag  + (size_t)r * K + cp * 8;
    const __nv_bfloat16* Bsrc = Btg + (size_t)r * K + cp * 8;
    uint32_t dstA0 = sBase + r * 64 + ((cp    ) ^ wkey) * 16;
    uint32_t dstA1 = sBase + r * 64 + ((cp + 1) ^ wkey) * 16;

    // fragment addressing
    int fkey  = ((lane & 15) >> 1) & 3;
    int khalf = lane >> 4;
    uint32_t aRow = (uint32_t)(wm * 64 + (lane & 15)) * 64;
    uint32_t bRow = (uint32_t)TILE_BYTES + (uint32_t)(wn * 32 + (lane & 15)) * 64;

    float acc[4][4][4];
#pragma unroll
    for (int i = 0; i < 4; i++)
#pragma unroll
        for (int j = 0; j < 4; j++)
#pragma unroll
            for (int k = 0; k < 4; k++) acc[i][j][k] = 0.f;

    int niter = K >> 5;

#pragma unroll
    for (int p = 0; p < 2; p++) {
        uint32_t sb = p * STAGE_BYTES;
        int k0 = p << 5;
        cpasync16(dstA0 + sb, Asrc + k0);
        cpasync16(dstA1 + sb, Asrc + k0 + 8);
        cpasync16(dstA0 + sb + TILE_BYTES, Bsrc + k0);
        cpasync16(dstA1 + sb + TILE_BYTES, Bsrc + k0 + 8);
        asm volatile("cp.async.commit_group;");
    }

    int st = 0;
    for (int it = 0; it < niter; ++it) {
        int pre = it + 2;
        if (pre < niter) {
            int ps = pre % NSTAGE;
            uint32_t sb = ps * STAGE_BYTES;
            int k0 = pre << 5;
            cpasync16(dstA0 + sb, Asrc + k0);
            cpasync16(dstA1 + sb, Asrc + k0 + 8);
            cpasync16(dstA0 + sb + TILE_BYTES, Bsrc + k0);
            cpasync16(dstA1 + sb + TILE_BYTES, Bsrc + k0 + 8);
        }
        asm volatile("cp.async.commit_group;");
        asm volatile("cp.async.wait_group 2;" ::: "memory");
        __syncthreads();

        uint32_t stb = st * STAGE_BYTES;
#pragma unroll
        for (int s = 0; s < 2; s++) {
            int chunk = s * 2 + khalf;
            uint32_t aoff = sBase + stb + aRow + ((chunk ^ fkey) * 16);
            uint32_t boff = sBase + stb + bRow + ((chunk ^ fkey) * 16);
            uint32_t a[4][4], b[4][2];
#pragma unroll
            for (int mi = 0; mi < 4; mi++)
                ldsm4(a[mi][0], a[mi][1], a[mi][2], a[mi][3], aoff + mi * 1024);
#pragma unroll
            for (int h = 0; h < 2; h++) {
                uint32_t q0, q1, q2, q3;
                ldsm4(q0, q1, q2, q3, boff + h * 1024);
                b[h * 2][0]     = q0; b[h * 2][1]     = q2;
                b[h * 2 + 1][0] = q1; b[h * 2 + 1][1] = q3;
            }
#pragma unroll
            for (int mi = 0; mi < 4; mi++)
#pragma unroll
                for (int ni = 0; ni < 4; ni++)
                    mma_bf16(acc[mi][ni], a[mi], b[ni]);
        }
        __syncthreads();
        st = (st + 1) % NSTAGE;
    }

    if (epi == 2) {
        // bias + residual, then transpose through smem and write [B,C,H,W].
        float* smf = (float*)smem;              // [64][132] fp32 = 33792 B
        float* outp = (float*)Cv;
        int t0 = by * 128;
        int b  = t0 >> 14;
        int p0 = t0 & (HW - 1);
        int c0 = bx * 128;
#pragma unroll
        for (int h = 0; h < 2; h++) {
            __syncthreads();
#pragma unroll
            for (int ni = 0; ni < 4; ni++) {
                int cl = wn * 32 + ni * 8 + (lane & 3) * 2;   // 0..127
                if ((cl >> 6) != h) continue;
                int cg = c0 + cl;
                float bi0 = bias[cg], bi1 = bias[cg + 1];
                int cc = cl & 63;
#pragma unroll
                for (int mi = 0; mi < 4; mi++) {
                    int rl = wm * 64 + mi * 16 + (lane >> 2);
                    size_t rg = (size_t)(t0 + rl);
                    float2 r0 = *(const float2*)(res + rg * 256 + cg);
                    float2 r1 = *(const float2*)(res + (rg + 8) * 256 + cg);
                    smf[cc * 132 + rl]           = acc[mi][ni][0] + bi0 + r0.x;
                    smf[(cc + 1) * 132 + rl]     = acc[mi][ni][1] + bi1 + r0.y;
                    smf[cc * 132 + rl + 8]       = acc[mi][ni][2] + bi0 + r1.x;
                    smf[(cc + 1) * 132 + rl + 8] = acc[mi][ni][3] + bi1 + r1.y;
                }
            }
            __syncthreads();
            int ch = tid >> 2, seg = tid & 3;
            float* op = outp + ((size_t)b * CCH + c0 + h * 64 + ch) * HW + p0;
            const float* sp = smf + ch * 132;
#pragma unroll
            for (int j = 0; j < 8; j++) {
                int idx = seg + 4 * j;
                ((float4*)op)[idx] = ((const float4*)sp)[idx];
            }
        }
        return;
    }

    // epi 0/1: bf16 output
    int colBase = bx * 128 + wn * 32;
    int rowBase = by * 128 + wm * 64 + (lane >> 2);
    __nv_bfloat16* Cb = (__nv_bfloat16*)Cv;
#pragma unroll
    for (int ni = 0; ni < 4; ni++) {
        int c = colBase + ni * 8 + (lane & 3) * 2;
        float bi0 = bias[c], bi1 = bias[c + 1];
#pragma unroll
        for (int mi = 0; mi < 4; mi++) {
            int rr = rowBase + mi * 16;
            float v00 = acc[mi][ni][0] + bi0;
            float v01 = acc[mi][ni][1] + bi1;
            float v10 = acc[mi][ni][2] + bi0;
            float v11 = acc[mi][ni][3] + bi1;
            if (epi == 1) {
                v00 = 0.5f * v00 * (1.f + erff(v00 * 0.70710678118654752f));
                v01 = 0.5f * v01 * (1.f + erff(v01 * 0.70710678118654752f));
                v10 = 0.5f * v10 * (1.f + erff(v10 * 0.70710678118654752f));
                v11 = 0.5f * v11 * (1.f + erff(v11 * 0.70710678118654752f));
            }
            *(__nv_bfloat162*)(Cb + (size_t)rr * N + c) =
                __floats2bfloat162_rn(v00, v01);
            *(__nv_bfloat162*)(Cb + (size_t)(rr + 8) * N + c) =
                __floats2bfloat162_rn(v10, v11);
        }
    }
}

// ---------------------------------------------------------------------------
// 3x3 neighborhood attention + residual + fused LN2; q/k/v bf16 packed [N,768]
// ---------------------------------------------------------------------------
__global__ __launch_bounds__(256) void attn_kernel(const float* __restrict__ g2,
                                                   const float* __restrict__ b2)
{
    int lane = threadIdx.x & 31;
    int warp = threadIdx.x >> 5;
    int t = blockIdx.x * 8 + warp;
    int p = t & (HW - 1);
    int yy = p >> 7, xx = p & 127;

    const __nv_bfloat162* qp = (const __nv_bfloat162*)(g_qkv + (size_t)t * 768) + lane;
    float2 ql[4];
#pragma unroll
    for (int i = 0; i < 4; i++) ql[i] = __bfloat1622float2(qp[32 * i]);

    float sc[9];
    int tns[9];
    unsigned vmask = 0;
#pragma unroll
    for (int n = 0; n < 9; n++) {
        int dy = n / 3 - 1, dx = n % 3 - 1;
        int ny = yy + dy, nx = xx + dx;
        bool valid = ((unsigned)ny < 128u) && ((unsigned)nx < 128u);
        int tn = t + dy * WD + dx;
        tns[n] = tn;
        if (valid) {
            vmask |= 1u << n;
            const __nv_bfloat162* kp =
                (const __nv_bfloat162*)(g_qkv + (size_t)tn * 768 + 256) + lane;
            float dot = 0.f;
#pragma unroll
            for (int i = 0; i < 4; i++) {
                float2 kv = __bfloat1622float2(kp[32 * i]);
                dot += ql[i].x * kv.x + ql[i].y * kv.y;
            }
#pragma unroll
            for (int off = 16; off >= 1; off >>= 1)
                dot += __shfl_xor_sync(0xffffffffu, dot, off);
            sc[n] = dot * (1.0f / 16.0f);
        } else {
            sc[n] = -1e30f;
        }
    }

    float mx = sc[0];
#pragma unroll
    for (int n = 1; n < 9; n++) mx = fmaxf(mx, sc[n]);
    float w[9], wsum = 0.f;
#pragma unroll
    for (int n = 0; n < 9; n++) {
        w[n] = ((vmask >> n) & 1u) ? expf(sc[n] - mx) : 0.f;
        wsum += w[n];
    }
    float inv = 1.f / wsum;

    float2 acc[4];
#pragma unroll
    for (int i = 0; i < 4; i++) acc[i] = make_float2(0.f, 0.f);
#pragma unroll
    for (int n = 0; n < 9; n++) {
        if ((vmask >> n) & 1u) {
            float wn = w[n] * inv;
            const __nv_bfloat162* vp =
                (const __nv_bfloat162*)(g_qkv + (size_t)tns[n] * 768 + 512) + lane;
#pragma unroll
            for (int i = 0; i < 4; i++) {
                float2 vv = __bfloat1622float2(vp[32 * i]);
                acc[i].x += wn * vv.x;
                acc[i].y += wn * vv.y;
            }
        }
    }

    const float2* xp = (const float2*)(g_xc + (size_t)t * CCH) + lane;
    float2 xv[4];
    float s1 = 0.f, s2 = 0.f;
#pragma unroll
    for (int i = 0; i < 4; i++) {
        float2 xr = xp[32 * i];
        xv[i].x = xr.x + acc[i].x;
        xv[i].y = xr.y + acc[i].y;
        s1 += xv[i].x + xv[i].y;
        s2 += xv[i].x * xv[i].x + xv[i].y * xv[i].y;
    }
#pragma unroll
    for (int off = 16; off >= 1; off >>= 1) {
        s1 += __shfl_xor_sync(0xffffffffu, s1, off);
        s2 += __shfl_xor_sync(0xffffffffu, s2, off);
    }
    float m1  = s1 * (1.f / 256.f);
    float var = fmaxf(s2 * (1.f / 256.f) - m1 * m1, 0.f);
    float rstd = rsqrtf(var + EPSF);

    float2* x1p = (float2*)(g_x1 + (size_t)t * CCH) + lane;
    __nv_bfloat162* n2p = (__nv_bfloat162*)(g_n2 + (size_t)t * CCH) + lane;
    const float2* g2p = (const float2*)g2 + lane;
    const float2* b2p = (const float2*)b2 + lane;
#pragma unroll
    for (int i = 0; i < 4; i++) {
        float2 gg = g2p[32 * i], bb = b2p[32 * i];
        x1p[32 * i] = xv[i];
        n2p[32 * i] = __floats2bfloat162_rn(
            (xv[i].x - m1) * rstd * gg.x + bb.x,
            (xv[i].y - m1) * rstd * gg.y + bb.y);
    }
}

// ---------------------------------------------------------------------------
extern "C" void kernel_launch(void* const* d_in, const int* in_sizes, int n_in,
                              void* d_out, int out_size)
{
    (void)in_sizes; (void)n_in; (void)out_size;
    const float* x     = (const float*)d_in[0];
    const float* wq    = (const float*)d_in[1];
    const float* bq    = (const float*)d_in[2];
    const float* wk    = (const float*)d_in[3];
    const float* bk    = (const float*)d_in[4];
    const float* wv    = (const float*)d_in[5];
    const float* bv    = (const float*)d_in[6];
    const float* ln1_g = (const float*)d_in[7];
    const float* ln1_b = (const float*)d_in[8];
    const float* ln2_g = (const float*)d_in[9];
    const float* ln2_b = (const float*)d_in[10];
    const float* fc1_w = (const float*)d_in[11];
    const float* fc1_b = (const float*)d_in[12];
    const float* fc2_w = (const float*)d_in[13];
    const float* fc2_b = (const float*)d_in[14];
    float* out = (float*)d_out;

    __nv_bfloat16 *pn1, *pn2, *ph, *pwqkv, *pw1, *pw2, *pqkv;
    float *px1, *pbqkv;
    cudaGetSymbolAddress((void**)&pn1,   g_n1);
    cudaGetSymbolAddress((void**)&pn2,   g_n2);
    cudaGetSymbolAddress((void**)&ph,    g_h);
    cudaGetSymbolAddress((void**)&pwqkv, g_wqkv_t);
    cudaGetSymbolAddress((void**)&pw1,   g_w1_t);
    cudaGetSymbolAddress((void**)&pw2,   g_w2_t);
    cudaGetSymbolAddress((void**)&pqkv,  g_qkv);
    cudaGetSymbolAddress((void**)&px1,   g_x1);
    cudaGetSymbolAddress((void**)&pbqkv, g_bqkv);

    cudaFuncSetAttribute(bgemm_kernel,
                         cudaFuncAttributeMaxDynamicSharedMemorySize, SMEM_TOTAL);

    // all weight transposes + bias packing in one launch
    wprep_kernel<<<704, dim3(32, 8)>>>(wq, wk, wv, fc1_w, fc2_w, bq, bk, bv);

    ln1_kernel<<<2048, 256>>>(x, ln1_g, ln1_b);

    // fused QKV: M=65536, N=768, K=256 -> bf16
    bgemm_kernel<<<dim3(6, 512), 256, SMEM_TOTAL>>>(pn1, pwqkv, pbqkv, nullptr,
                                                    pqkv, 768, 256, 0);

    attn_kernel<<<8192, 256>>>(ln2_g, ln2_b);

    // fc1 + GELU -> bf16 h
    bgemm_kernel<<<dim3(8, 512), 256, SMEM_TOTAL>>>(pn2, pw1, fc1_b, nullptr,
                                                    ph, 1024, 256, 1);
    // fc2 + bias + residual -> transposed fp32 out
    bgemm_kernel<<<dim3(2, 512), 256, SMEM_TOTAL>>>(ph, pw2, fc2_b, px1,
                                                    out, 256, 1024, 2);
}